// round 6
// baseline (speedup 1.0000x reference)
#include <cuda_runtime.h>
#include <math.h>

#define B 32
#define H 512
#define E 256
#define VV 32000
#define TT 64
#define KF 768          // E + H (per-step feature length)
#define WOUT_LD 1280    // 2H + E
#define PADF 772        // KF + 4 pad -> conflict-free LDS.128 (772/4=193, odd)
#define PADZ 516        // H + 4 pad

typedef unsigned long long u64;

// ---------------- persistent device scratch (no allocations) ----------------
__device__ float d_scratch[TT * B * VV];        // logits in (T, B, V) layout
__device__ float d_base[B * VV];                // z @ W_out_z^T + b_out
__device__ float d_cg[4 * H * B];               // z @ W_ih_z^T + b_ih + b_hh, [R][b]
__device__ float d_hbuf[2][B * H];              // double-buffered hidden state
__device__ float d_cbuf[B * H];                 // cell state
__device__ unsigned long long d_slot[TT * B];   // packed (orderable(max) << 32) | ~argmax

__device__ __forceinline__ unsigned long long packmax(float f, int v) {
    unsigned u = __float_as_uint(f);
    u = (u & 0x80000000u) ? ~u : (u | 0x80000000u);   // order-preserving float->uint
    return ((unsigned long long)u << 32) | (unsigned)(~v);  // ties -> smallest v wins
}

__device__ __forceinline__ float sigmoidf_(float x) { return 1.0f / (1.0f + expf(-x)); }

// Packed fp32x2 FMA (Blackwell): d = a*b + c elementwise on 2 packed floats.
__device__ __forceinline__ u64 fma2(u64 a, u64 b, u64 c) {
    u64 d;
    asm("fma.rn.f32x2 %0, %1, %2, %3;" : "=l"(d) : "l"(a), "l"(b), "l"(c));
    return d;
}
__device__ __forceinline__ float2 u2f(u64 v) {
    float2 r;
    asm("mov.b64 {%0, %1}, %2;" : "=f"(r.x), "=f"(r.y) : "l"(v));
    return r;
}

// ---------------- init: h, c, argmax slots ----------------
__global__ void initK(const float* __restrict__ h0, const float* __restrict__ c0) {
    int i = blockIdx.x * blockDim.x + threadIdx.x;
    if (i < B * H) { d_hbuf[0][i] = h0[i]; d_cbuf[i] = c0[i]; }
    if (i < TT * B) d_slot[i] = 0ULL;
}

// ---------------- precompute gate constants: cg[R][b] = z[b].W_ih[R,:512] + b_ih + b_hh ----------------
__global__ void constgateK(const float* __restrict__ h0, const float* __restrict__ Wih,
                           const float* __restrict__ bih, const float* __restrict__ bhh) {
    int gw = (blockIdx.x * blockDim.x + threadIdx.x) >> 5;   // 65536 warps
    int lane = threadIdx.x & 31;
    int b = gw & 31;
    int R = gw >> 5;                                          // [0, 2048)
    const float* z = h0 + b * H;
    const float* w = Wih + (long)R * KF;                      // cols [0:512) multiply z
    float a = 0.f;
    for (int k = lane; k < H; k += 32) a += w[k] * z[k];
    #pragma unroll
    for (int o = 16; o > 0; o >>= 1) a += __shfl_down_sync(0xffffffffu, a, o);
    if (lane == 0) d_cg[R * B + b] = a + bih[R] + bhh[R];
}

// ---------------- precompute base[b][v] = z[b].W_out[v,:512] + b_out[v] ----------------
__global__ __launch_bounds__(256, 2) void baseK(const float* __restrict__ h0,
        const float* __restrict__ Wout, const float* __restrict__ bout) {
    extern __shared__ float zs[];   // B * PADZ floats
    int tid = threadIdx.x;
    for (int i = tid; i < B * H; i += 256) {
        int b = i >> 9, k = i & 511;
        zs[b * PADZ + k] = h0[i];
    }
    __syncthreads();
    int warp = tid >> 5, lane = tid & 31;
    int v0 = blockIdx.x * 64 + warp * 8;
    u64 acc[16];
    #pragma unroll
    for (int i = 0; i < 16; i++) acc[i] = 0ULL;
    const ulonglong2* fb = (const ulonglong2*)(zs + lane * PADZ);
    const float* wb = Wout + (long)v0 * WOUT_LD;              // cols [0:512)
    #pragma unroll 4
    for (int k4 = 0; k4 < H / 4; k4++) {
        ulonglong2 f = fb[k4];
        #pragma unroll
        for (int i = 0; i < 8; i++) {
            ulonglong2 w = ((const ulonglong2*)(wb + (long)i * WOUT_LD))[k4];
            acc[2 * i]     = fma2(w.x, f.x, acc[2 * i]);
            acc[2 * i + 1] = fma2(w.y, f.y, acc[2 * i + 1]);
        }
    }
    float out8[8];
    #pragma unroll
    for (int i = 0; i < 8; i++) {
        float2 a = u2f(acc[2 * i]), b2 = u2f(acc[2 * i + 1]);
        out8[i] = (a.x + a.y) + (b2.x + b2.y) + bout[v0 + i];
    }
    float* op = d_base + (long)lane * VV + v0;
    *(float4*)(op)     = make_float4(out8[0], out8[1], out8[2], out8[3]);
    *(float4*)(op + 4) = make_float4(out8[4], out8[5], out8[6], out8[7]);
}

// ---------------- per-step LSTM gates: fused block GEMM + pointwise update ----------------
// Grid 32 blocks x 256 thr. Block handles j-range of 16 (all 4 gates = 64 rows).
// Warp w: gate g = w>>1, 8 rows j0 + (w&1)*8 .. +7. lane = b.
__global__ __launch_bounds__(256) void gates2K(int t, const int* __restrict__ y0,
        const float* __restrict__ emb, const float* __restrict__ Wih,
        const float* __restrict__ Whh) {
    extern __shared__ float fs[];                 // B * PADF: feat = [emb[y](256) | h_old(512)]
    __shared__ float gbuf[4 * 16 * 32];           // gate sums [g][jl][b]
    __shared__ int ys[B];
    int tid = threadIdx.x;
    if (tid < B) {
        ys[tid] = (t == 0) ? y0[tid]
                           : (int)(~(unsigned)(d_slot[(t - 1) * B + tid] & 0xFFFFFFFFull));
    }
    __syncthreads();
    const float* hold = d_hbuf[t & 1];
    for (int i = tid; i < B * KF; i += 256) {
        int b = i / KF, k = i - b * KF;
        fs[b * PADF + k] = (k < E) ? emb[(long)ys[b] * E + k] : hold[b * H + (k - E)];
    }
    __syncthreads();
    int warp = tid >> 5, lane = tid & 31;
    int g = warp >> 1;
    int jl0 = (warp & 1) * 8;
    int j0 = blockIdx.x * 16;
    int R0 = g * H + j0 + jl0;                    // 8 consecutive rows
    u64 acc[16];
    #pragma unroll
    for (int i = 0; i < 16; i++) acc[i] = 0ULL;
    // part 1: emb features x W_ih[R, 512:768)
    {
        const ulonglong2* fb = (const ulonglong2*)(fs + lane * PADF);
        const float* wb = Wih + (long)R0 * KF + 512;
        #pragma unroll 4
        for (int k4 = 0; k4 < E / 4; k4++) {
            ulonglong2 f = fb[k4];
            #pragma unroll
            for (int i = 0; i < 8; i++) {
                ulonglong2 w = ((const ulonglong2*)(wb + (long)i * KF))[k4];
                acc[2 * i]     = fma2(w.x, f.x, acc[2 * i]);
                acc[2 * i + 1] = fma2(w.y, f.y, acc[2 * i + 1]);
            }
        }
    }
    // part 2: h features x W_hh[R, :]
    {
        const ulonglong2* fb = (const ulonglong2*)(fs + lane * PADF + E);
        const float* wb = Whh + (long)R0 * H;
        #pragma unroll 4
        for (int k4 = 0; k4 < H / 4; k4++) {
            ulonglong2 f = fb[k4];
            #pragma unroll
            for (int i = 0; i < 8; i++) {
                ulonglong2 w = ((const ulonglong2*)(wb + (long)i * H))[k4];
                acc[2 * i]     = fma2(w.x, f.x, acc[2 * i]);
                acc[2 * i + 1] = fma2(w.y, f.y, acc[2 * i + 1]);
            }
        }
    }
    #pragma unroll
    for (int i = 0; i < 8; i++) {
        int R = R0 + i;
        float2 a = u2f(acc[2 * i]), b2 = u2f(acc[2 * i + 1]);
        float s = (a.x + a.y) + (b2.x + b2.y) + d_cg[R * B + lane];
        gbuf[(g * 16 + (jl0 + i)) * 32 + lane] = s;
    }
    __syncthreads();
    // pointwise LSTM update for this block's 16 j x 32 b
    for (int idx = tid; idx < 16 * 32; idx += 256) {
        int jl = idx >> 5, b = idx & 31;
        int j = j0 + jl;
        float ig = sigmoidf_(gbuf[(0 * 16 + jl) * 32 + b]);
        float fg = sigmoidf_(gbuf[(1 * 16 + jl) * 32 + b]);
        float gg = tanhf(gbuf[(2 * 16 + jl) * 32 + b]);
        float og = sigmoidf_(gbuf[(3 * 16 + jl) * 32 + b]);
        float c = fg * d_cbuf[b * H + j] + ig * gg;
        d_cbuf[b * H + j] = c;
        d_hbuf[(t + 1) & 1][b * H + j] = og * tanhf(c);
    }
}

// ---------------- per-step logits (K=768 part) + fused argmax ----------------
// 512 threads, 2 blocks/SM -> 32 warps/SM for latency cover. lane = b; warp owns 8 v rows.
__global__ __launch_bounds__(512, 2) void logitsK(int t, const int* __restrict__ y0,
        const float* __restrict__ emb, const float* __restrict__ Wout) {
    extern __shared__ float fs[];                 // B * PADF floats (feat = [emb[y] | h_new])
    __shared__ int ys[B];
    __shared__ unsigned long long red[16][B];
    int tid = threadIdx.x;
    if (tid < B) {
        ys[tid] = (t == 0) ? y0[tid]
                           : (int)(~(unsigned)(d_slot[(t - 1) * B + tid] & 0xFFFFFFFFull));
    }
    __syncthreads();
    const float* hc = d_hbuf[(t + 1) & 1];        // h written by gates2K this step
    for (int i = tid; i < B * KF; i += 512) {
        int b = i / KF, k = i - b * KF;
        fs[b * PADF + k] = (k < E) ? emb[(long)ys[b] * E + k] : hc[b * H + (k - E)];
    }
    __syncthreads();
    int warp = tid >> 5, lane = tid & 31;
    int v0 = blockIdx.x * 128 + warp * 8;
    u64 acc[16];
    #pragma unroll
    for (int i = 0; i < 16; i++) acc[i] = 0ULL;
    const ulonglong2* fb = (const ulonglong2*)(fs + lane * PADF);
    const float* wb = Wout + (long)v0 * WOUT_LD + 512;        // cols [512:1280)
    #pragma unroll 4
    for (int k4 = 0; k4 < KF / 4; k4++) {
        ulonglong2 f = fb[k4];
        #pragma unroll
        for (int i = 0; i < 8; i++) {
            ulonglong2 w = ((const ulonglong2*)(wb + (long)i * WOUT_LD))[k4];
            acc[2 * i]     = fma2(w.x, f.x, acc[2 * i]);
            acc[2 * i + 1] = fma2(w.y, f.y, acc[2 * i + 1]);
        }
    }
    float out8[8];
    float best = __int_as_float(0xff800000);      // -inf
    int bestv = 0;
    const float* bp = d_base + (long)lane * VV + v0;
    #pragma unroll
    for (int i = 0; i < 8; i++) {
        float2 a = u2f(acc[2 * i]), b2 = u2f(acc[2 * i + 1]);
        float s = (a.x + a.y) + (b2.x + b2.y) + bp[i];
        out8[i] = s;
        if (s > best) { best = s; bestv = v0 + i; }   // strict > keeps first occurrence
    }
    float* sp = d_scratch + ((long)t * B + lane) * VV + v0;
    *(float4*)(sp)     = make_float4(out8[0], out8[1], out8[2], out8[3]);
    *(float4*)(sp + 4) = make_float4(out8[4], out8[5], out8[6], out8[7]);
    red[warp][lane] = packmax(best, bestv);
    __syncthreads();
    if (warp == 0) {
        unsigned long long m = red[0][lane];
        #pragma unroll
        for (int w = 1; w < 16; w++) { unsigned long long x = red[w][lane]; if (x > m) m = x; }
        atomicMax(&d_slot[t * B + lane], m);
    }
}

// ---------------- final transpose (T, B, V) -> (B, V, T) ----------------
__global__ void transposeK(float* __restrict__ out) {
    __shared__ float tile[32][33];
    int b  = blockIdx.z;
    int vt = blockIdx.x;     // V / 32 tiles
    int tt = blockIdx.y;     // T / 32 tiles
    int tx = threadIdx.x, ty = threadIdx.y;   // (32, 8)
    #pragma unroll
    for (int i = 0; i < 32; i += 8) {
        int t = tt * 32 + ty + i;
        int v = vt * 32 + tx;
        tile[ty + i][tx] = d_scratch[((long)t * B + b) * VV + v];
    }
    __syncthreads();
    #pragma unroll
    for (int i = 0; i < 32; i += 8) {
        int v = vt * 32 + ty + i;
        int t = tt * 32 + tx;
        out[((long)b * VV + v) * TT + t] = tile[tx][ty + i];
    }
}

// ---------------- launch ----------------
extern "C" void kernel_launch(void* const* d_in, const int* in_sizes, int n_in,
                              void* d_out, int out_size) {
    const int*   y0   = (const int*)d_in[0];
    const float* h0   = (const float*)d_in[1];
    const float* c0   = (const float*)d_in[2];
    const float* emb  = (const float*)d_in[3];
    const float* Wih  = (const float*)d_in[4];
    const float* Whh  = (const float*)d_in[5];
    const float* bih  = (const float*)d_in[6];
    const float* bhh  = (const float*)d_in[7];
    const float* Wout = (const float*)d_in[8];
    const float* bout = (const float*)d_in[9];
    float* out = (float*)d_out;

    int smemL = B * PADF * (int)sizeof(float);   // 98816 B
    int smemB = B * PADZ * (int)sizeof(float);   // 66048 B
    cudaFuncSetAttribute(logitsK, cudaFuncAttributeMaxDynamicSharedMemorySize, smemL);
    cudaFuncSetAttribute(gates2K, cudaFuncAttributeMaxDynamicSharedMemorySize, smemL);
    cudaFuncSetAttribute(baseK,   cudaFuncAttributeMaxDynamicSharedMemorySize, smemB);

    initK<<<64, 256>>>(h0, c0);
    constgateK<<<8192, 256>>>(h0, Wih, bih, bhh);   // 65536 warps: (b, R)
    baseK<<<VV / 64, 256, smemB>>>(h0, Wout, bout);

    for (int t = 0; t < TT; t++) {
        gates2K<<<H / 16, 256, smemL>>>(t, y0, emb, Wih, Whh);   // 32 blocks
        logitsK<<<VV / 128, 512, smemL>>>(t, y0, emb, Wout);     // 250 blocks
    }
    transposeK<<<dim3(VV / 32, TT / 32, B), dim3(32, 8)>>>(out);
}

// round 9
// speedup vs baseline: 1.8234x; 1.8234x over previous
#include <cuda_runtime.h>
#include <math.h>

#define B 32
#define H 512
#define E 256
#define VV 32000
#define TT 64
#define KF 768          // E + H (per-step feature length)
#define WOUT_LD 1280    // 2H + E
#define PADF 772        // KF + 4 pad
#define PADZ 516        // H + 4 pad

typedef unsigned long long u64;

// ---------------- persistent device scratch (no allocations) ----------------
__device__ float d_scratch[TT * B * VV];        // logits in (T, B, V) layout
__device__ float d_base[B * VV];                // z @ W_out_z^T + b_out
__device__ float d_cg[4 * H * B];               // z @ W_ih_z^T + b_ih + b_hh, [R][b]
__device__ float d_hbuf[2][B * H];              // double-buffered hidden state
__device__ float d_cbuf[B * H];                 // cell state
__device__ u64 d_slot[TT * B];                  // packed (orderable(max) << 32) | ~argmax

__device__ __forceinline__ u64 packmax(float f, int v) {
    unsigned u = __float_as_uint(f);
    u = (u & 0x80000000u) ? ~u : (u | 0x80000000u);   // order-preserving float->uint
    return ((u64)u << 32) | (unsigned)(~v);           // ties -> smallest v wins
}

__device__ __forceinline__ float sigmoidf_(float x) { return 1.0f / (1.0f + expf(-x)); }

// Packed fp32x2 FMA (Blackwell)
__device__ __forceinline__ u64 fma2(u64 a, u64 b, u64 c) {
    u64 d;
    asm("fma.rn.f32x2 %0, %1, %2, %3;" : "=l"(d) : "l"(a), "l"(b), "l"(c));
    return d;
}
__device__ __forceinline__ float2 u2f(u64 v) {
    float2 r;
    asm("mov.b64 {%0, %1}, %2;" : "=f"(r.x), "=f"(r.y) : "l"(v));
    return r;
}
// 16B shared load as two u64 k-pairs
__device__ __forceinline__ void lds128(u64& a, u64& b, unsigned saddr) {
    asm("ld.shared.v2.u64 {%0, %1}, [%2];" : "=l"(a), "=l"(b) : "r"(saddr));
}

// ---------------- init ----------------
__global__ void initK(const float* __restrict__ h0, const float* __restrict__ c0) {
    int i = blockIdx.x * blockDim.x + threadIdx.x;
    if (i < B * H) { d_hbuf[0][i] = h0[i]; d_cbuf[i] = c0[i]; }
    if (i < TT * B) d_slot[i] = 0ULL;
}

// ---------------- precompute cg[R][b] = z[b].W_ih[R,:512] + b_ih + b_hh ----------------
__global__ void constgateK(const float* __restrict__ h0, const float* __restrict__ Wih,
                           const float* __restrict__ bih, const float* __restrict__ bhh) {
    int gw = (blockIdx.x * blockDim.x + threadIdx.x) >> 5;
    int lane = threadIdx.x & 31;
    int b = gw & 31;
    int R = gw >> 5;
    const float* z = h0 + b * H;
    const float* w = Wih + (long)R * KF;
    float a = 0.f;
    for (int k = lane; k < H; k += 32) a += w[k] * z[k];
    #pragma unroll
    for (int o = 16; o > 0; o >>= 1) a += __shfl_down_sync(0xffffffffu, a, o);
    if (lane == 0) d_cg[R * B + b] = a + bih[R] + bhh[R];
}

// ---------------- precompute base[b][v] = z[b].W_out[v,:512] + b_out[v] ----------------
// v-per-lane microkernel (same shape as logitsK, K=512).
__global__ __launch_bounds__(128, 2) void baseK(const float* __restrict__ h0,
        const float* __restrict__ Wout, const float* __restrict__ bout) {
    extern __shared__ float zs[];   // B * PADZ floats
    int tid = threadIdx.x;
    for (int i = tid; i < B * (H / 4); i += 128) {
        int b = i / (H / 4), k = (i % (H / 4)) * 4;
        *(float4*)(zs + b * PADZ + k) = *(const float4*)(h0 + b * H + k);
    }
    __syncthreads();
    int warp = tid >> 5, lane = tid & 31;
    int v = blockIdx.x * 128 + warp * 32 + lane;
    const float* wrow = Wout + (long)v * WOUT_LD;     // cols [0:512)
    u64 acc[32];
    #pragma unroll
    for (int i = 0; i < 32; i++) acc[i] = 0ULL;
    unsigned zsb = (unsigned)__cvta_generic_to_shared(zs);
    #pragma unroll 2
    for (int k0 = 0; k0 < H; k0 += 4) {
        ulonglong2 w2 = *(const ulonglong2*)(wrow + k0);
        #pragma unroll
        for (int b = 0; b < 32; b++) {
            u64 fa, fb;
            lds128(fa, fb, zsb + (unsigned)(b * PADZ + k0) * 4u);
            acc[b] = fma2(w2.x, fa, acc[b]);
            acc[b] = fma2(w2.y, fb, acc[b]);
        }
    }
    float bo = bout[v];
    #pragma unroll
    for (int b = 0; b < 32; b++) {
        float2 p = u2f(acc[b]);
        d_base[(long)b * VV + v] = p.x + p.y + bo;
    }
}

// ---------------- per-step fused LSTM gates ----------------
// 64 blocks x 256 thr. Block: j-range 8 x 4 gates = 32 rows (lane = g*8+jl).
// Warps split K 8 ways (96 k each); smem partial reduce + pointwise update.
__global__ __launch_bounds__(256) void gatesF(int t, const int* __restrict__ y0,
        const float* __restrict__ emb, const float* __restrict__ Wih,
        const float* __restrict__ Whh) {
    extern __shared__ float fs[];                 // B*PADF feat | 8*1056 partials
    float* part = fs + B * PADF;
    __shared__ int ys[B];
    int tid = threadIdx.x;
    if (tid < B)
        ys[tid] = (t == 0) ? y0[tid]
                           : (int)(~(unsigned)(d_slot[(t - 1) * B + tid] & 0xFFFFFFFFull));
    __syncthreads();
    const float* hold = d_hbuf[t & 1];
    for (int i = tid; i < B * (KF / 4); i += 256) {
        int b = i / (KF / 4), k = (i % (KF / 4)) * 4;
        float4 v = (k < E) ? *(const float4*)(emb + (long)ys[b] * E + k)
                           : *(const float4*)(hold + b * H + (k - E));
        *(float4*)(fs + b * PADF + k) = v;
    }
    __syncthreads();
    int warp = tid >> 5, lane = tid & 31;
    int g = lane >> 3, jl = lane & 7;
    int j = blockIdx.x * 8 + jl;
    int R = g * H + j;
    int klo = warp * 96, khi = klo + 96;
    u64 acc[32];
    #pragma unroll
    for (int i = 0; i < 32; i++) acc[i] = 0ULL;
    unsigned fsb = (unsigned)__cvta_generic_to_shared(fs);
    const float* w1 = Wih + (long)R * KF + 512;       // k in [0,256): emb part
    const float* w2p = Whh + (long)R * H - E;         // k in [256,768): h part
    int kmid = khi < E ? khi : E;
    for (int k0 = klo; k0 < kmid; k0 += 4) {
        ulonglong2 w2 = *(const ulonglong2*)(w1 + k0);
        #pragma unroll
        for (int b = 0; b < 32; b++) {
            u64 fa, fb;
            lds128(fa, fb, fsb + (unsigned)(b * PADF + k0) * 4u);
            acc[b] = fma2(w2.x, fa, acc[b]);
            acc[b] = fma2(w2.y, fb, acc[b]);
        }
    }
    int kst = klo > E ? klo : E;
    for (int k0 = kst; k0 < khi; k0 += 4) {
        ulonglong2 w2 = *(const ulonglong2*)(w2p + k0);
        #pragma unroll
        for (int b = 0; b < 32; b++) {
            u64 fa, fb;
            lds128(fa, fb, fsb + (unsigned)(b * PADF + k0) * 4u);
            acc[b] = fma2(w2.x, fa, acc[b]);
            acc[b] = fma2(w2.y, fb, acc[b]);
        }
    }
    #pragma unroll
    for (int b = 0; b < 32; b++) {
        float2 p = u2f(acc[b]);
        part[warp * 1056 + lane * 33 + b] = p.x + p.y;
    }
    __syncthreads();
    // pointwise: thread = (jj, b)
    int jj = tid >> 5, b = tid & 31;
    float gv[4];
    #pragma unroll
    for (int g2 = 0; g2 < 4; g2++) {
        int ln = g2 * 8 + jj;
        float s = 0.f;
        #pragma unroll
        for (int kc = 0; kc < 8; kc++) s += part[kc * 1056 + ln * 33 + b];
        gv[g2] = s + d_cg[(g2 * H + blockIdx.x * 8 + jj) * B + b];
    }
    float ig = sigmoidf_(gv[0]);
    float fg = sigmoidf_(gv[1]);
    float gg = tanhf(gv[2]);
    float og = sigmoidf_(gv[3]);
    int jg = blockIdx.x * 8 + jj;
    float c = fg * d_cbuf[b * H + jg] + ig * gg;
    d_cbuf[b * H + jg] = c;
    d_hbuf[(t + 1) & 1][b * H + jg] = og * tanhf(c);
}

// ---------------- per-step logits (K=768 part) + fused argmax ----------------
// lane = v row; acc over all 32 b as fp32x2 (k-even,k-odd) pairs.
__global__ __launch_bounds__(128, 2) void logitsK(int t, const int* __restrict__ y0,
        const float* __restrict__ emb, const float* __restrict__ Wout) {
    extern __shared__ float fs[];                 // B * PADF
    __shared__ int ys[B];
    __shared__ u64 red[4][B];
    int tid = threadIdx.x;
    if (tid < B)
        ys[tid] = (t == 0) ? y0[tid]
                           : (int)(~(unsigned)(d_slot[(t - 1) * B + tid] & 0xFFFFFFFFull));
    __syncthreads();
    const float* hc = d_hbuf[(t + 1) & 1];
    for (int i = tid; i < B * (KF / 4); i += 128) {
        int b = i / (KF / 4), k = (i % (KF / 4)) * 4;
        float4 v = (k < E) ? *(const float4*)(emb + (long)ys[b] * E + k)
                           : *(const float4*)(hc + b * H + (k - E));
        *(float4*)(fs + b * PADF + k) = v;
    }
    __syncthreads();
    int warp = tid >> 5, lane = tid & 31;
    int v = blockIdx.x * 128 + warp * 32 + lane;
    const float* wrow = Wout + (long)v * WOUT_LD + 512;   // cols [512:1280)
    u64 acc[32];
    #pragma unroll
    for (int i = 0; i < 32; i++) acc[i] = 0ULL;
    unsigned fsb = (unsigned)__cvta_generic_to_shared(fs);
    #pragma unroll 2
    for (int k0 = 0; k0 < KF; k0 += 4) {
        ulonglong2 w2 = *(const ulonglong2*)(wrow + k0);
        #pragma unroll
        for (int b = 0; b < 32; b++) {
            u64 fa, fb;
            lds128(fa, fb, fsb + (unsigned)(b * PADF + k0) * 4u);
            acc[b] = fma2(w2.x, fa, acc[b]);
            acc[b] = fma2(w2.y, fb, acc[b]);
        }
    }
    // epilogue: add base, store (T,B,V), per-b argmax across lanes
    #pragma unroll
    for (int b = 0; b < 32; b++) {
        float2 p = u2f(acc[b]);
        float s = p.x + p.y + d_base[(long)b * VV + v];
        d_scratch[((long)t * B + b) * VV + v] = s;
        u64 pm = packmax(s, v);
        #pragma unroll
        for (int o = 16; o > 0; o >>= 1) {
            u64 q = __shfl_xor_sync(0xffffffffu, pm, o);
            if (q > pm) pm = q;
        }
        if (lane == 0) red[warp][b] = pm;
    }
    __syncthreads();
    if (tid < B) {
        u64 m = red[0][tid];
        #pragma unroll
        for (int w = 1; w < 4; w++) if (red[w][tid] > m) m = red[w][tid];
        atomicMax(&d_slot[t * B + tid], m);
    }
}

// ---------------- final transpose (T, B, V) -> (B, V, T) ----------------
__global__ void transposeK(float* __restrict__ out) {
    __shared__ float tile[32][33];
    int b  = blockIdx.z;
    int vt = blockIdx.x;
    int tt = blockIdx.y;
    int tx = threadIdx.x, ty = threadIdx.y;   // (32, 8)
    #pragma unroll
    for (int i = 0; i < 32; i += 8) {
        int t = tt * 32 + ty + i;
        int v = vt * 32 + tx;
        tile[ty + i][tx] = d_scratch[((long)t * B + b) * VV + v];
    }
    __syncthreads();
    #pragma unroll
    for (int i = 0; i < 32; i += 8) {
        int v = vt * 32 + ty + i;
        int t = tt * 32 + tx;
        out[((long)b * VV + v) * TT + t] = tile[tx][ty + i];
    }
}

// ---------------- launch ----------------
extern "C" void kernel_launch(void* const* d_in, const int* in_sizes, int n_in,
                              void* d_out, int out_size) {
    const int*   y0   = (const int*)d_in[0];
    const float* h0   = (const float*)d_in[1];
    const float* c0   = (const float*)d_in[2];
    const float* emb  = (const float*)d_in[3];
    const float* Wih  = (const float*)d_in[4];
    const float* Whh  = (const float*)d_in[5];
    const float* bih  = (const float*)d_in[6];
    const float* bhh  = (const float*)d_in[7];
    const float* Wout = (const float*)d_in[8];
    const float* bout = (const float*)d_in[9];
    float* out = (float*)d_out;

    int smemL = B * PADF * (int)sizeof(float);             // 98816 B
    int smemG = (B * PADF + 8 * 1056) * (int)sizeof(float);// 132608 B
    int smemB = B * PADZ * (int)sizeof(float);             // 66048 B
    cudaFuncSetAttribute(logitsK, cudaFuncAttributeMaxDynamicSharedMemorySize, smemL);
    cudaFuncSetAttribute(gatesF,  cudaFuncAttributeMaxDynamicSharedMemorySize, smemG);
    cudaFuncSetAttribute(baseK,   cudaFuncAttributeMaxDynamicSharedMemorySize, smemB);

    initK<<<64, 256>>>(h0, c0);
    constgateK<<<8192, 256>>>(h0, Wih, bih, bhh);
    baseK<<<VV / 128, 128, smemB>>>(h0, Wout, bout);

    for (int t = 0; t < TT; t++) {
        gatesF<<<64, 256, smemG>>>(t, y0, emb, Wih, Whh);
        logitsK<<<VV / 128, 128, smemL>>>(t, y0, emb, Wout);
    }
    transposeK<<<dim3(VV / 32, TT / 32, B), dim3(32, 8)>>>(out);
}

// round 10
// speedup vs baseline: 1.8356x; 1.0067x over previous
#include <cuda_runtime.h>
#include <math.h>

#define B 32
#define H 512
#define E 256
#define VV 32000
#define TT 64
#define KF 768          // E + H (per-step feature length)
#define WOUT_LD 1280    // 2H + E
#define PADZ 516        // H + 4 pad (baseK only)

typedef unsigned long long u64;

// ---------------- persistent device scratch (no allocations) ----------------
__device__ float d_scratch[TT * B * VV];        // logits in (T, B, V) layout
__device__ float d_base[B * VV];                // z @ W_out_z^T + b_out
__device__ float d_cg[4 * H * B];               // z @ W_ih_z^T + b_ih + b_hh, [R][b]
__device__ float d_hbuf[2][B * H];              // double-buffered hidden state
__device__ float d_cbuf[B * H];                 // cell state
__device__ u64 d_slot[TT * B];                  // packed (orderable(max) << 32) | ~argmax

__device__ __forceinline__ u64 packmax(float f, int v) {
    unsigned u = __float_as_uint(f);
    u = (u & 0x80000000u) ? ~u : (u | 0x80000000u);   // order-preserving float->uint
    return ((u64)u << 32) | (unsigned)(~v);           // ties -> smallest v wins
}

__device__ __forceinline__ float sigmoidf_(float x) { return 1.0f / (1.0f + expf(-x)); }

// Packed fp32x2 FMA (Blackwell)
__device__ __forceinline__ u64 fma2(u64 a, u64 b, u64 c) {
    u64 d;
    asm("fma.rn.f32x2 %0, %1, %2, %3;" : "=l"(d) : "l"(a), "l"(b), "l"(c));
    return d;
}
__device__ __forceinline__ float2 u2f(u64 v) {
    float2 r;
    asm("mov.b64 {%0, %1}, %2;" : "=f"(r.x), "=f"(r.y) : "l"(v));
    return r;
}
// 16B shared load as two u64 k-pairs
__device__ __forceinline__ void lds128(u64& a, u64& b, unsigned saddr) {
    asm("ld.shared.v2.u64 {%0, %1}, [%2];" : "=l"(a), "=l"(b) : "r"(saddr));
}

// ---------------- init ----------------
__global__ void initK(const float* __restrict__ h0, const float* __restrict__ c0) {
    int i = blockIdx.x * blockDim.x + threadIdx.x;
    if (i < B * H) { d_hbuf[0][i] = h0[i]; d_cbuf[i] = c0[i]; }
    if (i < TT * B) d_slot[i] = 0ULL;
}

// ---------------- precompute cg[R][b] = z[b].W_ih[R,:512] + b_ih + b_hh ----------------
__global__ void constgateK(const float* __restrict__ h0, const float* __restrict__ Wih,
                           const float* __restrict__ bih, const float* __restrict__ bhh) {
    int gw = (blockIdx.x * blockDim.x + threadIdx.x) >> 5;
    int lane = threadIdx.x & 31;
    int b = gw & 31;
    int R = gw >> 5;
    const float* z = h0 + b * H;
    const float* w = Wih + (long)R * KF;
    float a = 0.f;
    for (int k = lane; k < H; k += 32) a += w[k] * z[k];
    #pragma unroll
    for (int o = 16; o > 0; o >>= 1) a += __shfl_down_sync(0xffffffffu, a, o);
    if (lane == 0) d_cg[R * B + b] = a + bih[R] + bhh[R];
}

// ---------------- precompute base[b][v] = z[b].W_out[v,:512] + b_out[v] ----------------
__global__ __launch_bounds__(128, 2) void baseK(const float* __restrict__ h0,
        const float* __restrict__ Wout, const float* __restrict__ bout) {
    extern __shared__ float zs[];   // B * PADZ floats
    int tid = threadIdx.x;
    for (int i = tid; i < B * (H / 4); i += 128) {
        int b = i / (H / 4), k = (i % (H / 4)) * 4;
        *(float4*)(zs + b * PADZ + k) = *(const float4*)(h0 + b * H + k);
    }
    __syncthreads();
    int warp = tid >> 5, lane = tid & 31;
    int v = blockIdx.x * 128 + warp * 32 + lane;
    const float* wrow = Wout + (long)v * WOUT_LD;     // cols [0:512)
    u64 acc[32];
    #pragma unroll
    for (int i = 0; i < 32; i++) acc[i] = 0ULL;
    unsigned zsb = (unsigned)__cvta_generic_to_shared(zs);
    for (int kb = 0; kb < H; kb += 16) {
        ulonglong2 w[4];
        #pragma unroll
        for (int i = 0; i < 4; i++) w[i] = *(const ulonglong2*)(wrow + kb + i * 4);
        #pragma unroll
        for (int i = 0; i < 4; i++) {
            #pragma unroll
            for (int b = 0; b < 32; b++) {
                u64 fa, fb;
                lds128(fa, fb, zsb + (unsigned)(b * PADZ + kb + i * 4) * 4u);
                acc[b] = fma2(w[i].x, fa, acc[b]);
                acc[b] = fma2(w[i].y, fb, acc[b]);
            }
        }
    }
    float bo = bout[v];
    #pragma unroll
    for (int b = 0; b < 32; b++) {
        float2 p = u2f(acc[b]);
        d_base[(long)b * VV + v] = p.x + p.y + bo;
    }
}

// ---------------- per-step fused LSTM gates ----------------
// 128 blocks x 256 thr. Block: j-range 4 x 4 gates = 16 rows.
// lane = row*2 + half (half picks b range of 16). Warps split K 8 ways (96 k).
__global__ __launch_bounds__(256) void gatesF(int t, const int* __restrict__ y0,
        const float* __restrict__ emb, const float* __restrict__ Wih,
        const float* __restrict__ Whh) {
    extern __shared__ float fs[];                 // B*768 feat | 8*528 partials
    float* part = fs + B * 768;
    int* ys = (int*)part;                         // alias: used before part written
    int tid = threadIdx.x;
    if (tid < B)
        ys[tid] = (t == 0) ? y0[tid]
                           : (int)(~(unsigned)(d_slot[(t - 1) * B + tid] & 0xFFFFFFFFull));
    __syncthreads();
    const float* hold = d_hbuf[t & 1];
    for (int i = tid; i < B * (KF / 4); i += 256) {
        int b = i / (KF / 4), k = (i % (KF / 4)) * 4;
        float4 v = (k < E) ? *(const float4*)(emb + (long)ys[b] * E + k)
                           : *(const float4*)(hold + b * H + (k - E));
        *(float4*)(fs + b * 768 + k) = v;
    }
    __syncthreads();
    int warp = tid >> 5, lane = tid & 31;
    int row = lane >> 1, bh = lane & 1, b0 = bh << 4;
    int g = row >> 2, jl = row & 3;
    int j = blockIdx.x * 4 + jl;
    int R = g * H + j;
    int klo = warp * 96, khi = klo + 96;
    u64 acc[16];
    #pragma unroll
    for (int i = 0; i < 16; i++) acc[i] = 0ULL;
    unsigned fsb = (unsigned)__cvta_generic_to_shared(fs);
    const float* w1 = Wih + (long)R * KF + 512;       // k in [0,256): emb part
    const float* w2p = Whh + (long)R * H - E;         // k in [256,768): h part
    int kmid = khi < E ? khi : E;
    for (int k0 = klo; k0 < kmid; k0 += 4) {
        ulonglong2 w2 = *(const ulonglong2*)(w1 + k0);
        #pragma unroll
        for (int bb = 0; bb < 16; bb++) {
            u64 fa, fb;
            lds128(fa, fb, fsb + (unsigned)((b0 + bb) * 768 + k0) * 4u);
            acc[bb] = fma2(w2.x, fa, acc[bb]);
            acc[bb] = fma2(w2.y, fb, acc[bb]);
        }
    }
    int kst = klo > E ? klo : E;
    for (int k0 = kst; k0 < khi; k0 += 4) {
        ulonglong2 w2 = *(const ulonglong2*)(w2p + k0);
        #pragma unroll
        for (int bb = 0; bb < 16; bb++) {
            u64 fa, fb;
            lds128(fa, fb, fsb + (unsigned)((b0 + bb) * 768 + k0) * 4u);
            acc[bb] = fma2(w2.x, fa, acc[bb]);
            acc[bb] = fma2(w2.y, fb, acc[bb]);
        }
    }
    #pragma unroll
    for (int bb = 0; bb < 16; bb++) {
        float2 p = u2f(acc[bb]);
        part[warp * 528 + row * 33 + b0 + bb] = p.x + p.y;
    }
    __syncthreads();
    // pointwise: thread = (jj, b) for 4 j x 32 b
    if (tid < 128) {
        int jj = tid >> 5, b = tid & 31;
        float gv[4];
        #pragma unroll
        for (int g2 = 0; g2 < 4; g2++) {
            int ln = g2 * 4 + jj;
            float s = 0.f;
            #pragma unroll
            for (int w = 0; w < 8; w++) s += part[w * 528 + ln * 33 + b];
            gv[g2] = s + d_cg[(g2 * H + blockIdx.x * 4 + jj) * B + b];
        }
        float ig = sigmoidf_(gv[0]);
        float fg = sigmoidf_(gv[1]);
        float gg = tanhf(gv[2]);
        float og = sigmoidf_(gv[3]);
        int jg = blockIdx.x * 4 + jj;
        float c = fg * d_cbuf[b * H + jg] + ig * gg;
        d_cbuf[b * H + jg] = c;
        d_hbuf[(t + 1) & 1][b * H + jg] = og * tanhf(c);
    }
}

// ---------------- per-step logits (K=768 part) + fused argmax ----------------
// 250 blocks x 256 thr (16 warps/SM). Block covers 128 v; warps 2-way K-split.
// lane = v; acc over 32 b as fp32x2 (k-even,k-odd) pairs; 4-deep weight prefetch.
__global__ __launch_bounds__(256, 2) void logitsK(int t, const int* __restrict__ y0,
        const float* __restrict__ emb, const float* __restrict__ Wout) {
    extern __shared__ float fs[];                 // B*768 feat | 32*128 partials
    float* part = fs + B * 768;
    int* ys = (int*)part;                         // alias: dead before part written
    u64* red = (u64*)fs;                          // alias: feat dead after GEMM barrier
    int tid = threadIdx.x;
    if (tid < B)
        ys[tid] = (t == 0) ? y0[tid]
                           : (int)(~(unsigned)(d_slot[(t - 1) * B + tid] & 0xFFFFFFFFull));
    __syncthreads();
    const float* hc = d_hbuf[(t + 1) & 1];
    for (int i = tid; i < B * (KF / 4); i += 256) {
        int b = i / (KF / 4), k = (i % (KF / 4)) * 4;
        float4 v = (k < E) ? *(const float4*)(emb + (long)ys[b] * E + k)
                           : *(const float4*)(hc + b * H + (k - E));
        *(float4*)(fs + b * 768 + k) = v;
    }
    __syncthreads();
    int warp = tid >> 5, lane = tid & 31;
    int wv = warp & 3, kr = warp >> 2;
    int vl = wv * 32 + lane;
    int v = blockIdx.x * 128 + vl;
    int klo = kr * 384;
    const float* wrow = Wout + (long)v * WOUT_LD + 512 + klo;
    u64 acc[32];
    #pragma unroll
    for (int i = 0; i < 32; i++) acc[i] = 0ULL;
    unsigned fsb = (unsigned)__cvta_generic_to_shared(fs);
    for (int kb = 0; kb < 384; kb += 16) {
        ulonglong2 w[4];
        #pragma unroll
        for (int i = 0; i < 4; i++) w[i] = *(const ulonglong2*)(wrow + kb + i * 4);
        #pragma unroll
        for (int i = 0; i < 4; i++) {
            #pragma unroll
            for (int b = 0; b < 32; b++) {
                u64 fa, fb;
                lds128(fa, fb, fsb + (unsigned)(b * 768 + klo + kb + i * 4) * 4u);
                acc[b] = fma2(w[i].x, fa, acc[b]);
                acc[b] = fma2(w[i].y, fb, acc[b]);
            }
        }
    }
    if (kr == 1) {
        #pragma unroll
        for (int b = 0; b < 32; b++) {
            float2 p = u2f(acc[b]);
            part[b * 128 + vl] = p.x + p.y;
        }
    }
    __syncthreads();                              // partials ready; feat now dead
    if (kr == 0) {
        #pragma unroll
        for (int b = 0; b < 32; b++) {
            float2 p = u2f(acc[b]);
            float s = p.x + p.y + part[b * 128 + vl] + d_base[(long)b * VV + v];
            d_scratch[((long)t * B + b) * VV + v] = s;
            u64 pm = packmax(s, v);
            #pragma unroll
            for (int o = 16; o > 0; o >>= 1) {
                u64 q = __shfl_xor_sync(0xffffffffu, pm, o);
                if (q > pm) pm = q;
            }
            if (lane == 0) red[wv * 32 + b] = pm;
        }
    }
    __syncthreads();
    if (tid < B) {
        u64 m = red[tid];
        #pragma unroll
        for (int w = 1; w < 4; w++) if (red[w * 32 + tid] > m) m = red[w * 32 + tid];
        atomicMax(&d_slot[t * B + tid], m);
    }
}

// ---------------- final transpose (T, B, V) -> (B, V, T) ----------------
__global__ void transposeK(float* __restrict__ out) {
    __shared__ float tile[32][33];
    int b  = blockIdx.z;
    int vt = blockIdx.x;
    int tt = blockIdx.y;
    int tx = threadIdx.x, ty = threadIdx.y;   // (32, 8)
    #pragma unroll
    for (int i = 0; i < 32; i += 8) {
        int t = tt * 32 + ty + i;
        int v = vt * 32 + tx;
        tile[ty + i][tx] = d_scratch[((long)t * B + b) * VV + v];
    }
    __syncthreads();
    #pragma unroll
    for (int i = 0; i < 32; i += 8) {
        int v = vt * 32 + ty + i;
        int t = tt * 32 + tx;
        out[((long)b * VV + v) * TT + t] = tile[tx][ty + i];
    }
}

// ---------------- launch ----------------
extern "C" void kernel_launch(void* const* d_in, const int* in_sizes, int n_in,
                              void* d_out, int out_size) {
    const int*   y0   = (const int*)d_in[0];
    const float* h0   = (const float*)d_in[1];
    const float* c0   = (const float*)d_in[2];
    const float* emb  = (const float*)d_in[3];
    const float* Wih  = (const float*)d_in[4];
    const float* Whh  = (const float*)d_in[5];
    const float* bih  = (const float*)d_in[6];
    const float* bhh  = (const float*)d_in[7];
    const float* Wout = (const float*)d_in[8];
    const float* bout = (const float*)d_in[9];
    float* out = (float*)d_out;

    int smemL = (B * 768 + 32 * 128) * (int)sizeof(float);   // 114688 B -> 2 blocks/SM
    int smemG = (B * 768 + 8 * 528) * (int)sizeof(float);    // 115200 B
    int smemB = B * PADZ * (int)sizeof(float);               // 66048 B
    cudaFuncSetAttribute(logitsK, cudaFuncAttributeMaxDynamicSharedMemorySize, smemL);
    cudaFuncSetAttribute(gatesF,  cudaFuncAttributeMaxDynamicSharedMemorySize, smemG);
    cudaFuncSetAttribute(baseK,   cudaFuncAttributeMaxDynamicSharedMemorySize, smemB);

    initK<<<64, 256>>>(h0, c0);
    constgateK<<<8192, 256>>>(h0, Wih, bih, bhh);
    baseK<<<VV / 128, 128, smemB>>>(h0, Wout, bout);

    for (int t = 0; t < TT; t++) {
        gatesF<<<128, 256, smemG>>>(t, y0, emb, Wih, Whh);
        logitsK<<<VV / 128, 256, smemL>>>(t, y0, emb, Wout);
    }
    transposeK<<<dim3(VV / 32, TT / 32, B), dim3(32, 8)>>>(out);
}

// round 12
// speedup vs baseline: 1.9757x; 1.0763x over previous
#include <cuda_runtime.h>
#include <math.h>

#define B 32
#define H 512
#define E 256
#define VV 32000
#define TT 64
#define KF 768          // E + H (per-step feature length)
#define WOUT_LD 1280    // 2H + E
#define PADZ 516        // H + 4 pad (baseK only)
#define WTLD 20         // weight tile row stride (16 + 4): 80B = odd multiple of 16B

typedef unsigned long long u64;

// ---------------- persistent device scratch (no allocations) ----------------
__device__ float d_scratch[TT * B * VV];        // logits in (T, B, V) layout
__device__ float d_base[B * VV];                // z @ W_out_z^T + b_out
__device__ float d_cg[4 * H * B];               // z @ W_ih_z^T + b_ih + b_hh, [R][b]
__device__ float d_hbuf[2][B * H];              // double-buffered hidden state
__device__ float d_cbuf[B * H];                 // cell state
__device__ u64 d_slot[TT * B];                  // packed (orderable(max) << 32) | ~argmax

__device__ __forceinline__ u64 packmax(float f, int v) {
    unsigned u = __float_as_uint(f);
    u = (u & 0x80000000u) ? ~u : (u | 0x80000000u);   // order-preserving float->uint
    return ((u64)u << 32) | (unsigned)(~v);           // ties -> smallest v wins
}

__device__ __forceinline__ float sigmoidf_(float x) { return 1.0f / (1.0f + expf(-x)); }

// Packed fp32x2 FMA (Blackwell)
__device__ __forceinline__ u64 fma2(u64 a, u64 b, u64 c) {
    u64 d;
    asm("fma.rn.f32x2 %0, %1, %2, %3;" : "=l"(d) : "l"(a), "l"(b), "l"(c));
    return d;
}
__device__ __forceinline__ float2 u2f(u64 v) {
    float2 r;
    asm("mov.b64 {%0, %1}, %2;" : "=f"(r.x), "=f"(r.y) : "l"(v));
    return r;
}
// 16B shared load as two u64 k-pairs
__device__ __forceinline__ void lds128(u64& a, u64& b, unsigned saddr) {
    asm("ld.shared.v2.u64 {%0, %1}, [%2];" : "=l"(a), "=l"(b) : "r"(saddr));
}

// ---------------- init ----------------
__global__ void initK(const float* __restrict__ h0, const float* __restrict__ c0) {
    int i = blockIdx.x * blockDim.x + threadIdx.x;
    if (i < B * H) { d_hbuf[0][i] = h0[i]; d_cbuf[i] = c0[i]; }
    if (i < TT * B) d_slot[i] = 0ULL;
}

// ---------------- precompute cg[R][b] = z[b].W_ih[R,:512] + b_ih + b_hh ----------------
__global__ void constgateK(const float* __restrict__ h0, const float* __restrict__ Wih,
                           const float* __restrict__ bih, const float* __restrict__ bhh) {
    int gw = (blockIdx.x * blockDim.x + threadIdx.x) >> 5;
    int lane = threadIdx.x & 31;
    int b = gw & 31;
    int R = gw >> 5;
    const float* z = h0 + b * H;
    const float* w = Wih + (long)R * KF;
    float a = 0.f;
    for (int k = lane; k < H; k += 32) a += w[k] * z[k];
    #pragma unroll
    for (int o = 16; o > 0; o >>= 1) a += __shfl_down_sync(0xffffffffu, a, o);
    if (lane == 0) d_cg[R * B + b] = a + bih[R] + bhh[R];
}

// ---------------- precompute base[b][v] = z[b].W_out[v,:512] + b_out[v] ----------------
__global__ __launch_bounds__(128, 2) void baseK(const float* __restrict__ h0,
        const float* __restrict__ Wout, const float* __restrict__ bout) {
    extern __shared__ float zs[];   // B * PADZ floats
    int tid = threadIdx.x;
    for (int i = tid; i < B * (H / 4); i += 128) {
        int b = i / (H / 4), k = (i % (H / 4)) * 4;
        *(float4*)(zs + b * PADZ + k) = *(const float4*)(h0 + b * H + k);
    }
    __syncthreads();
    int warp = tid >> 5, lane = tid & 31;
    int v = blockIdx.x * 128 + warp * 32 + lane;
    const float* wrow = Wout + (long)v * WOUT_LD;     // cols [0:512)
    u64 acc[32];
    #pragma unroll
    for (int i = 0; i < 32; i++) acc[i] = 0ULL;
    unsigned zsb = (unsigned)__cvta_generic_to_shared(zs);
    for (int kb = 0; kb < H; kb += 16) {
        ulonglong2 w[4];
        #pragma unroll
        for (int i = 0; i < 4; i++) w[i] = *(const ulonglong2*)(wrow + kb + i * 4);
        #pragma unroll
        for (int i = 0; i < 4; i++) {
            #pragma unroll
            for (int b = 0; b < 32; b++) {
                u64 fa, fb;
                lds128(fa, fb, zsb + (unsigned)(b * PADZ + kb + i * 4) * 4u);
                acc[b] = fma2(w[i].x, fa, acc[b]);
                acc[b] = fma2(w[i].y, fb, acc[b]);
            }
        }
    }
    float bo = bout[v];
    #pragma unroll
    for (int b = 0; b < 32; b++) {
        float2 p = u2f(acc[b]);
        d_base[(long)b * VV + v] = p.x + p.y + bo;
    }
}

// ---------------- per-step fused LSTM gates ----------------
// 128 blocks x 256 thr. Block: 4 j x 4 gates = 16 rows; lane = row*2 + b-half.
// Warps split K 8 ways (96 k); chunk-16 with 4-deep batched weight loads.
__global__ __launch_bounds__(256) void gatesF(int t, const int* __restrict__ y0,
        const float* __restrict__ emb, const float* __restrict__ Wih,
        const float* __restrict__ Whh) {
    extern __shared__ float fs[];                 // B*768 feat | 8*528 partials
    float* part = fs + B * 768;
    int* ys = (int*)part;                         // alias: used before part written
    int tid = threadIdx.x;
    if (tid < B)
        ys[tid] = (t == 0) ? y0[tid]
                           : (int)(~(unsigned)(d_slot[(t - 1) * B + tid] & 0xFFFFFFFFull));
    __syncthreads();
    const float* hold = d_hbuf[t & 1];
    for (int i = tid; i < B * (KF / 4); i += 256) {
        int b = i / (KF / 4), k = (i % (KF / 4)) * 4;
        float4 v = (k < E) ? *(const float4*)(emb + (long)ys[b] * E + k)
                           : *(const float4*)(hold + b * H + (k - E));
        *(float4*)(fs + b * 768 + k) = v;
    }
    __syncthreads();
    int warp = tid >> 5, lane = tid & 31;
    int row = lane >> 1, bh = lane & 1, b0 = bh << 4;
    int g = row >> 2, jl = row & 3;
    int j = blockIdx.x * 4 + jl;
    int R = g * H + j;
    int klo = warp * 96;
    u64 acc[16];
    #pragma unroll
    for (int i = 0; i < 16; i++) acc[i] = 0ULL;
    unsigned fsb = (unsigned)__cvta_generic_to_shared(fs);
    const float* w1  = Wih + (long)R * KF + 512;      // k in [0,256): emb part
    const float* w2p = Whh + (long)R * H - E;         // k in [256,768): h part
    // 96-k segment = 6 chunks of 16; chunks never straddle E=256 (all bounds x16)
    for (int kc = klo; kc < klo + 96; kc += 16) {
        const float* wp = (kc < E) ? (w1 + kc) : (w2p + kc);
        ulonglong2 w[4];
        #pragma unroll
        for (int i = 0; i < 4; i++) w[i] = *(const ulonglong2*)(wp + i * 4);
        #pragma unroll
        for (int i = 0; i < 4; i++) {
            #pragma unroll
            for (int bb = 0; bb < 16; bb++) {
                u64 fa, fb;
                lds128(fa, fb, fsb + (unsigned)((b0 + bb) * 768 + kc + i * 4) * 4u);
                acc[bb] = fma2(w[i].x, fa, acc[bb]);
                acc[bb] = fma2(w[i].y, fb, acc[bb]);
            }
        }
    }
    #pragma unroll
    for (int bb = 0; bb < 16; bb++) {
        float2 p = u2f(acc[bb]);
        part[warp * 528 + row * 33 + b0 + bb] = p.x + p.y;
    }
    __syncthreads();
    // pointwise: thread = (jj, b) for 4 j x 32 b
    if (tid < 128) {
        int jj = tid >> 5, b = tid & 31;
        float gv[4];
        #pragma unroll
        for (int g2 = 0; g2 < 4; g2++) {
            int ln = g2 * 4 + jj;
            float s = 0.f;
            #pragma unroll
            for (int w = 0; w < 8; w++) s += part[w * 528 + ln * 33 + b];
            gv[g2] = s + d_cg[(g2 * H + blockIdx.x * 4 + jj) * B + b];
        }
        float ig = sigmoidf_(gv[0]);
        float fg = sigmoidf_(gv[1]);
        float gg = tanhf(gv[2]);
        float og = sigmoidf_(gv[3]);
        int jg = blockIdx.x * 4 + jj;
        float c = fg * d_cbuf[b * H + jg] + ig * gg;
        d_cbuf[b * H + jg] = c;
        d_hbuf[(t + 1) & 1][b * H + jg] = og * tanhf(c);
    }
}

// ---------------- per-step logits (K=768 part) + fused argmax ----------------
// 250 blocks x 128 thr (2 blocks/SM). Block = 128 v, full K.
// Weights staged per 16-k chunk through smem: 512 float4s = 4 loads/thread,
// coalesced LDG, register-pipelined one chunk ahead.
__global__ __launch_bounds__(128, 2) void logitsK(int t, const int* __restrict__ y0,
        const float* __restrict__ emb, const float* __restrict__ Wout) {
    extern __shared__ float fs[];                 // B*768 feat | 128*WTLD weight tile
    float* wt = fs + B * 768;
    int* ys = (int*)wt;                           // alias: dead before wt written
    u64* red = (u64*)wt;                          // alias: wt dead after final chunk sync
    int tid = threadIdx.x;
    if (tid < B)
        ys[tid] = (t == 0) ? y0[tid]
                           : (int)(~(unsigned)(d_slot[(t - 1) * B + tid] & 0xFFFFFFFFull));
    __syncthreads();
    const float* hc = d_hbuf[(t + 1) & 1];
    for (int i = tid; i < B * (KF / 4); i += 128) {
        int b = i / (KF / 4), k = (i % (KF / 4)) * 4;
        float4 v = (k < E) ? *(const float4*)(emb + (long)ys[b] * E + k)
                           : *(const float4*)(hc + b * H + (k - E));
        *(float4*)(fs + b * 768 + k) = v;
    }
    __syncthreads();                              // ys reads done; wt region free
    int warp = tid >> 5, lane = tid & 31;
    int vl = warp * 32 + lane;
    int v = blockIdx.x * 128 + vl;
    // tile: 128 rows x 16 floats = 512 float4s; thread loads rows tid>>2 + {0,32,64,96}
    int q = tid & 3;
    int r0 = tid >> 2;
    const float* gbase = Wout + ((long)blockIdx.x * 128 + r0) * WOUT_LD + 512 + q * 4;
    const float* g1 = gbase;
    const float* g2 = gbase + 32 * WOUT_LD;
    const float* g3 = gbase + 64 * WOUT_LD;
    const float* g4 = gbase + 96 * WOUT_LD;
    float* s1 = wt + r0 * WTLD + q * 4;
    float* s2 = s1 + 32 * WTLD;
    float* s3 = s1 + 64 * WTLD;
    float* s4 = s1 + 96 * WTLD;
    u64 acc[32];
    #pragma unroll
    for (int i = 0; i < 32; i++) acc[i] = 0ULL;
    unsigned fsb = (unsigned)__cvta_generic_to_shared(fs);
    unsigned wlb = (unsigned)__cvta_generic_to_shared(wt + vl * WTLD);
    float4 p1 = *(const float4*)(g1);             // preload chunk 0
    float4 p2 = *(const float4*)(g2);
    float4 p3 = *(const float4*)(g3);
    float4 p4 = *(const float4*)(g4);
    for (int kb = 0; kb < KF; kb += 16) {
        *(float4*)s1 = p1;
        *(float4*)s2 = p2;
        *(float4*)s3 = p3;
        *(float4*)s4 = p4;
        __syncthreads();
        if (kb + 16 < KF) {                       // prefetch next chunk into regs
            p1 = *(const float4*)(g1 + kb + 16);
            p2 = *(const float4*)(g2 + kb + 16);
            p3 = *(const float4*)(g3 + kb + 16);
            p4 = *(const float4*)(g4 + kb + 16);
        }
        #pragma unroll
        for (int i = 0; i < 4; i++) {
            u64 wx, wy;
            lds128(wx, wy, wlb + (unsigned)(i * 16));
            #pragma unroll
            for (int b = 0; b < 32; b++) {
                u64 fa, fb;
                lds128(fa, fb, fsb + (unsigned)(b * 768 + kb + i * 4) * 4u);
                acc[b] = fma2(wx, fa, acc[b]);
                acc[b] = fma2(wy, fb, acc[b]);
            }
        }
        __syncthreads();
    }
    // epilogue: add base, store (T,B,V), per-b argmax across lanes
    #pragma unroll
    for (int b = 0; b < 32; b++) {
        float2 p = u2f(acc[b]);
        float s = p.x + p.y + d_base[(long)b * VV + v];
        d_scratch[((long)t * B + b) * VV + v] = s;
        u64 pm = packmax(s, v);
        #pragma unroll
        for (int o = 16; o > 0; o >>= 1) {
            u64 qq = __shfl_xor_sync(0xffffffffu, pm, o);
            if (qq > pm) pm = qq;
        }
        if (lane == 0) red[warp * 32 + b] = pm;
    }
    __syncthreads();
    if (tid < B) {
        u64 m = red[tid];
        #pragma unroll
        for (int w = 1; w < 4; w++) if (red[w * 32 + tid] > m) m = red[w * 32 + tid];
        atomicMax(&d_slot[t * B + tid], m);
    }
}

// ---------------- final transpose (T, B, V) -> (B, V, T) ----------------
__global__ void transposeK(float* __restrict__ out) {
    __shared__ float tile[32][33];
    int b  = blockIdx.z;
    int vt = blockIdx.x;
    int tt = blockIdx.y;
    int tx = threadIdx.x, ty = threadIdx.y;   // (32, 8)
    #pragma unroll
    for (int i = 0; i < 32; i += 8) {
        int t = tt * 32 + ty + i;
        int v = vt * 32 + tx;
        tile[ty + i][tx] = d_scratch[((long)t * B + b) * VV + v];
    }
    __syncthreads();
    #pragma unroll
    for (int i = 0; i < 32; i += 8) {
        int v = vt * 32 + ty + i;
        int t = tt * 32 + tx;
        out[((long)b * VV + v) * TT + t] = tile[tx][ty + i];
    }
}

// ---------------- launch ----------------
extern "C" void kernel_launch(void* const* d_in, const int* in_sizes, int n_in,
                              void* d_out, int out_size) {
    const int*   y0   = (const int*)d_in[0];
    const float* h0   = (const float*)d_in[1];
    const float* c0   = (const float*)d_in[2];
    const float* emb  = (const float*)d_in[3];
    const float* Wih  = (const float*)d_in[4];
    const float* Whh  = (const float*)d_in[5];
    const float* bih  = (const float*)d_in[6];
    const float* bhh  = (const float*)d_in[7];
    const float* Wout = (const float*)d_in[8];
    const float* bout = (const float*)d_in[9];
    float* out = (float*)d_out;

    int smemL = (B * 768 + 128 * WTLD) * (int)sizeof(float);  // 108544 B -> 2 blocks/SM
    int smemG = (B * 768 + 8 * 528) * (int)sizeof(float);     // 115200 B
    int smemB = B * PADZ * (int)sizeof(float);                // 66048 B
    cudaFuncSetAttribute(logitsK, cudaFuncAttributeMaxDynamicSharedMemorySize, smemL);
    cudaFuncSetAttribute(gatesF,  cudaFuncAttributeMaxDynamicSharedMemorySize, smemG);
    cudaFuncSetAttribute(baseK,   cudaFuncAttributeMaxDynamicSharedMemorySize, smemB);

    initK<<<64, 256>>>(h0, c0);
    constgateK<<<8192, 256>>>(h0, Wih, bih, bhh);
    baseK<<<VV / 128, 128, smemB>>>(h0, Wout, bout);

    for (int t = 0; t < TT; t++) {
        gatesF<<<128, 256, smemG>>>(t, y0, emb, Wih, Whh);
        logitsK<<<VV / 128, 128, smemL>>>(t, y0, emb, Wout);
    }
    transposeK<<<dim3(VV / 32, TT / 32, B), dim3(32, 8)>>>(out);
}